// round 8
// baseline (speedup 1.0000x reference)
#include <cuda_runtime.h>
#include <cuda_bf16.h>
#include <mma.h>

using namespace nvcuda;

#define MAXN 50000
#define MAXE 1000000
#define MT2  782          // ceil(50000/64) m-tiles for the wmma GEMMs

typedef unsigned int u32;

// ---------------- scratch (device globals, no allocation) -------------------
__device__ __align__(16) float g_dinv[MAXN];
__device__ __align__(16) float g_buf1[MAXN * 128];   // A1, then A2
__device__ __align__(16) float g_buf2[MAXN * 128];   // T2
__device__ int g_cnt[MAXN];
__device__ int g_off[MAXN];
__device__ int g_pos[MAXN];
__device__ int g_srt[MAXE];
// pre-split bf16 weights (plain row-major)
__device__ __align__(16) __nv_bfloat16 g_w1hi[128 * 512], g_w1lo[128 * 512];
__device__ __align__(16) __nv_bfloat16 g_w3hi[512 * 128], g_w3lo[512 * 128];
// H1 split bf16, row-major [MT2*64][512]
__device__ __align__(16) __nv_bfloat16 g_h1hi[MT2 * 64 * 512];
__device__ __align__(16) __nv_bfloat16 g_h1lo[MT2 * 64 * 512];

// ---------------- helpers -----------------------------------------------------
__device__ __forceinline__ float leaky(float v) { return v >= 0.f ? v : 0.01f * v; }

__device__ __forceinline__ unsigned short f2bf(float v) {
    __nv_bfloat16 h = __float2bfloat16_rn(v);
    return static_cast<__nv_bfloat16_raw>(h).x;
}
__device__ __forceinline__ float bf2f(unsigned short u) {
    __nv_bfloat16_raw r; r.x = u;
    return __bfloat162float(__nv_bfloat16(r));
}
__device__ __forceinline__ void bsplit(float v, unsigned short& h, unsigned short& l) {
    h = f2bf(v);
    l = f2bf(v - bf2f(h));
}

// ---------------- CSR build (proven) ------------------------------------------
__global__ void k_zero(int n) {
    int i = blockIdx.x * blockDim.x + threadIdx.x;
    if (i < n) g_cnt[i] = 0;
}
__global__ void k_hist(const int* __restrict__ ei, int E) {
    int i = blockIdx.x * blockDim.x + threadIdx.x;
    if (i < E) atomicAdd(&g_cnt[ei[E + i]], 1);
}
__global__ void __launch_bounds__(1024) k_scan(int n) {
    __shared__ int tmp[1024];
    int tid = threadIdx.x;
    int chunk = (n + 1023) >> 10;
    int start = tid * chunk;
    int end = start + chunk; if (end > n) end = n;
    int s = 0;
    for (int i = start; i < end; i++) s += g_cnt[i];
    tmp[tid] = s;
    __syncthreads();
    for (int off = 1; off < 1024; off <<= 1) {
        int v = (tid >= off) ? tmp[tid - off] : 0;
        __syncthreads();
        tmp[tid] += v;
        __syncthreads();
    }
    int base = tmp[tid] - s;
    for (int i = start; i < end; i++) {
        g_off[i] = base; g_pos[i] = base;
        base += g_cnt[i];
        g_dinv[i] = rsqrtf((float)(g_cnt[i] + 1));
    }
}
__global__ void k_scatter(const int* __restrict__ ei, int E) {
    int i = blockIdx.x * blockDim.x + threadIdx.x;
    if (i >= E) return;
    int d = ei[E + i];
    int p = atomicAdd(&g_pos[d], 1);
    g_srt[p] = ei[i];
}

// ---------------- pull aggregation (proven) ------------------------------------
__global__ void __launch_bounds__(256) k_pull(const float* __restrict__ xin,
                                              int pass, int n) {
    int node = (blockIdx.x * blockDim.x + threadIdx.x) >> 5;
    int lane = threadIdx.x & 31;
    if (node >= n) return;
    const float* in = pass ? g_buf2 : xin;
    int off = g_off[node], cnt = g_cnt[node];
    float dd = g_dinv[node];

    float4 v = reinterpret_cast<const float4*>(in + (size_t)node * 128)[lane];
    float4 acc;
    acc.x = dd * v.x; acc.y = dd * v.y; acc.z = dd * v.z; acc.w = dd * v.w;

    int j = 0;
    for (; j + 3 < cnt; j += 4) {
        int s0 = g_srt[off + j],     s1 = g_srt[off + j + 1];
        int s2 = g_srt[off + j + 2], s3 = g_srt[off + j + 3];
        float w0 = g_dinv[s0], w1 = g_dinv[s1];
        float w2 = g_dinv[s2], w3 = g_dinv[s3];
        float4 a = reinterpret_cast<const float4*>(in + (size_t)s0 * 128)[lane];
        float4 b = reinterpret_cast<const float4*>(in + (size_t)s1 * 128)[lane];
        float4 c = reinterpret_cast<const float4*>(in + (size_t)s2 * 128)[lane];
        float4 e = reinterpret_cast<const float4*>(in + (size_t)s3 * 128)[lane];
        acc.x += w0 * a.x + w1 * b.x + w2 * c.x + w3 * e.x;
        acc.y += w0 * a.y + w1 * b.y + w2 * c.y + w3 * e.y;
        acc.z += w0 * a.z + w1 * b.z + w2 * c.z + w3 * e.z;
        acc.w += w0 * a.w + w1 * b.w + w2 * c.w + w3 * e.w;
    }
    for (; j < cnt; j++) {
        int s0 = g_srt[off + j];
        float w0 = g_dinv[s0];
        float4 a = reinterpret_cast<const float4*>(in + (size_t)s0 * 128)[lane];
        acc.x += w0 * a.x; acc.y += w0 * a.y; acc.z += w0 * a.z; acc.w += w0 * a.w;
    }
    acc.x *= dd; acc.y *= dd; acc.z *= dd; acc.w *= dd;
    reinterpret_cast<float4*>(g_buf1 + (size_t)node * 128)[lane] = acc;
}

// ---------------- weight prep: bf16 hi/lo split (row-major) --------------------
__global__ void k_prep_w1(const float* __restrict__ W1) {
    int idx = blockIdx.x * blockDim.x + threadIdx.x;
    if (idx >= 128 * 512) return;
    unsigned short h, l;
    bsplit(W1[idx], h, l);
    ((unsigned short*)g_w1hi)[idx] = h;
    ((unsigned short*)g_w1lo)[idx] = l;
}
__global__ void k_prep_w3(const float* __restrict__ W3) {
    int idx = blockIdx.x * blockDim.x + threadIdx.x;
    if (idx >= 512 * 128) return;
    unsigned short h, l;
    bsplit(W3[idx], h, l);
    ((unsigned short*)g_w3hi)[idx] = h;
    ((unsigned short*)g_w3lo)[idx] = l;
}

// smem layout for both wmma GEMMs (96 KB dynamic):
//   s_ahi [64][128] bf16 16KB | s_alo 16KB | s_bhi [128][128] bf16 32KB | s_blo 32KB
//   epilogue fp32 tile [64][128] (32KB) overlaps s_bhi region after compute.
#define WS_ALO 8192          /* in bf16 elements: 64*128 */
#define WS_BHI 16384
#define WS_BLO 32768
#define WS_TOTAL_BYTES 98304

// ---------------- GEMM1: H1 = leaky(A1 @ W1 + b1) -> bf16 hi/lo ---------------
// grid (MT2, 4); block 256 = 8 warps (4m x 2n); out tile 64x128
__global__ void __launch_bounds__(256) k_wgemm1(const float* __restrict__ b1, int n) {
    extern __shared__ __nv_bfloat16 sh[];
    __nv_bfloat16* s_ahi = sh;
    __nv_bfloat16* s_alo = sh + WS_ALO;
    __nv_bfloat16* s_bhi = sh + WS_BHI;
    __nv_bfloat16* s_blo = sh + WS_BLO;

    int tid = threadIdx.x;
    int wid = tid >> 5;
    int base = blockIdx.x * 64;
    int ns = blockIdx.y;            // n-slice 0..3 -> cols ns*128..+127 of 512

    // A tile: split fp32 -> bf16 hi/lo
    for (int it = tid; it < 64 * 32; it += 256) {
        int r = it >> 5, c4 = (it & 31) << 2;
        float4 v = make_float4(0.f, 0.f, 0.f, 0.f);
        if (base + r < n)
            v = reinterpret_cast<const float4*>(g_buf1 + (size_t)(base + r) * 128)[it & 31];
        ushort4 h, l;
        bsplit(v.x, h.x, l.x); bsplit(v.y, h.y, l.y);
        bsplit(v.z, h.z, l.z); bsplit(v.w, h.w, l.w);
        *reinterpret_cast<ushort4*>(s_ahi + r * 128 + c4) = h;
        *reinterpret_cast<ushort4*>(s_alo + r * 128 + c4) = l;
    }
    // B tile: copy pre-split W1 slice [128][128] out of [128][512]
    for (int it = tid; it < 128 * 16; it += 256) {
        int r = it >> 4, c8 = (it & 15) << 3;
        *reinterpret_cast<uint4*>(s_bhi + r * 128 + c8) =
            *reinterpret_cast<const uint4*>(g_w1hi + r * 512 + ns * 128 + c8);
        *reinterpret_cast<uint4*>(s_blo + r * 128 + c8) =
            *reinterpret_cast<const uint4*>(g_w1lo + r * 512 + ns * 128 + c8);
    }
    __syncthreads();

    int wm = wid & 3;       // rows wm*16
    int wn = wid >> 2;      // cols wn*64
    wmma::fragment<wmma::accumulator, 16, 16, 16, float> acc[4];
#pragma unroll
    for (int j = 0; j < 4; j++) wmma::fill_fragment(acc[j], 0.f);

#pragma unroll
    for (int ks = 0; ks < 8; ks++) {
        wmma::fragment<wmma::matrix_a, 16, 16, 16, __nv_bfloat16, wmma::row_major> ahi, alo;
        wmma::load_matrix_sync(ahi, s_ahi + (wm * 16) * 128 + ks * 16, 128);
        wmma::load_matrix_sync(alo, s_alo + (wm * 16) * 128 + ks * 16, 128);
#pragma unroll
        for (int j = 0; j < 4; j++) {
            wmma::fragment<wmma::matrix_b, 16, 16, 16, __nv_bfloat16, wmma::row_major> bhi, blo;
            wmma::load_matrix_sync(bhi, s_bhi + (ks * 16) * 128 + wn * 64 + j * 16, 128);
            wmma::load_matrix_sync(blo, s_blo + (ks * 16) * 128 + wn * 64 + j * 16, 128);
            wmma::mma_sync(acc[j], ahi, bhi, acc[j]);
            wmma::mma_sync(acc[j], alo, bhi, acc[j]);
            wmma::mma_sync(acc[j], ahi, blo, acc[j]);
        }
    }
    __syncthreads();   // done reading B region; reuse as fp32 epilogue tile

    float* e = reinterpret_cast<float*>(s_bhi);   // [64][128] fp32
#pragma unroll
    for (int j = 0; j < 4; j++)
        wmma::store_matrix_sync(e + (wm * 16) * 128 + wn * 64 + j * 16, acc[j],
                                128, wmma::mem_row_major);
    __syncthreads();

    // bias + leaky + split -> gmem H1 (row-major [.][512])
    for (int it = tid; it < 64 * 32; it += 256) {
        int r = it >> 5, c4 = (it & 31) << 2;
        if (base + r >= n) continue;
        float4 v = *reinterpret_cast<float4*>(e + r * 128 + c4);
        float4 bb = *reinterpret_cast<const float4*>(b1 + ns * 128 + c4);
        v.x = leaky(v.x + bb.x); v.y = leaky(v.y + bb.y);
        v.z = leaky(v.z + bb.z); v.w = leaky(v.w + bb.w);
        ushort4 h, l;
        bsplit(v.x, h.x, l.x); bsplit(v.y, h.y, l.y);
        bsplit(v.z, h.z, l.z); bsplit(v.w, h.w, l.w);
        size_t o = (size_t)(base + r) * 512 + ns * 128 + c4;
        *reinterpret_cast<ushort4*>((unsigned short*)g_h1hi + o) = h;
        *reinterpret_cast<ushort4*>((unsigned short*)g_h1lo + o) = l;
    }
}

// ---------------- GEMM2: T2 = H1 @ W3 -> fp32 ---------------------------------
// grid (MT2); block 256; out tile 64x128, K=512 in 4 chunks
__global__ void __launch_bounds__(256) k_wgemm2(int n) {
    extern __shared__ __nv_bfloat16 sh[];
    __nv_bfloat16* s_ahi = sh;
    __nv_bfloat16* s_alo = sh + WS_ALO;
    __nv_bfloat16* s_bhi = sh + WS_BHI;
    __nv_bfloat16* s_blo = sh + WS_BLO;

    int tid = threadIdx.x;
    int wid = tid >> 5;
    int base = blockIdx.x * 64;
    int wm = wid & 3;
    int wn = wid >> 2;

    wmma::fragment<wmma::accumulator, 16, 16, 16, float> acc[4];
#pragma unroll
    for (int j = 0; j < 4; j++) wmma::fill_fragment(acc[j], 0.f);

    for (int kc = 0; kc < 4; kc++) {
        // A chunk: H1 bf16 hi/lo rows base..+63, cols kc*128..+127
        for (int it = tid; it < 64 * 16; it += 256) {
            int r = it >> 4, c8 = (it & 15) << 3;
            uint4 h = make_uint4(0, 0, 0, 0), l = make_uint4(0, 0, 0, 0);
            if (base + r < n) {
                size_t o = (size_t)(base + r) * 512 + kc * 128 + c8;
                h = *reinterpret_cast<const uint4*>((const unsigned short*)g_h1hi + o);
                l = *reinterpret_cast<const uint4*>((const unsigned short*)g_h1lo + o);
            }
            *reinterpret_cast<uint4*>(s_ahi + r * 128 + c8) = h;
            *reinterpret_cast<uint4*>(s_alo + r * 128 + c8) = l;
        }
        // B chunk: W3 rows kc*128..+127, all 128 cols
        for (int it = tid; it < 128 * 16; it += 256) {
            int r = it >> 4, c8 = (it & 15) << 3;
            *reinterpret_cast<uint4*>(s_bhi + r * 128 + c8) =
                *reinterpret_cast<const uint4*>(g_w3hi + (kc * 128 + r) * 128 + c8);
            *reinterpret_cast<uint4*>(s_blo + r * 128 + c8) =
                *reinterpret_cast<const uint4*>(g_w3lo + (kc * 128 + r) * 128 + c8);
        }
        __syncthreads();

#pragma unroll
        for (int ks = 0; ks < 8; ks++) {
            wmma::fragment<wmma::matrix_a, 16, 16, 16, __nv_bfloat16, wmma::row_major> ahi, alo;
            wmma::load_matrix_sync(ahi, s_ahi + (wm * 16) * 128 + ks * 16, 128);
            wmma::load_matrix_sync(alo, s_alo + (wm * 16) * 128 + ks * 16, 128);
#pragma unroll
            for (int j = 0; j < 4; j++) {
                wmma::fragment<wmma::matrix_b, 16, 16, 16, __nv_bfloat16, wmma::row_major> bhi, blo;
                wmma::load_matrix_sync(bhi, s_bhi + (ks * 16) * 128 + wn * 64 + j * 16, 128);
                wmma::load_matrix_sync(blo, s_blo + (ks * 16) * 128 + wn * 64 + j * 16, 128);
                wmma::mma_sync(acc[j], ahi, bhi, acc[j]);
                wmma::mma_sync(acc[j], alo, bhi, acc[j]);
                wmma::mma_sync(acc[j], ahi, blo, acc[j]);
            }
        }
        __syncthreads();
    }

    float* e = reinterpret_cast<float*>(s_bhi);
#pragma unroll
    for (int j = 0; j < 4; j++)
        wmma::store_matrix_sync(e + (wm * 16) * 128 + wn * 64 + j * 16, acc[j],
                                128, wmma::mem_row_major);
    __syncthreads();

    for (int it = tid; it < 64 * 32; it += 256) {
        int r = it >> 5, c4 = (it & 31) << 2;
        if (base + r >= n) continue;
        float4 v = *reinterpret_cast<float4*>(e + r * 128 + c4);
        *reinterpret_cast<float4*>(g_buf2 + (size_t)(base + r) * 128 + c4) = v;
    }
}

// ---------------- head (proven scalar version) ---------------------------------
__global__ void __launch_bounds__(256) k_final(
    const float* __restrict__ b3,
    const float* __restrict__ fc1w, const float* __restrict__ fc1b,
    const float* __restrict__ fc2w, const float* __restrict__ fc2b,
    float* __restrict__ out, int n) {
    __shared__ float h2s[32][128];
    __shared__ float red[32][8];

    int tid = threadIdx.x;
    int base = blockIdx.x * 32;
    int valid = n - base; if (valid > 32) valid = 32;

    for (int idx = tid; idx < 32 * 32; idx += 256) {
        int m = idx >> 5, c = idx & 31;
        float4 v = make_float4(0.f, 0.f, 0.f, 0.f);
        if (m < valid)
            v = reinterpret_cast<const float4*>(g_buf1 + (size_t)(base + m) * 128)[c];
        float4 bb = reinterpret_cast<const float4*>(b3)[c];
        v.x = leaky(v.x + bb.x); v.y = leaky(v.y + bb.y);
        v.z = leaky(v.z + bb.z); v.w = leaky(v.w + bb.w);
        reinterpret_cast<float4*>(&h2s[m][0])[c] = v;
    }
    __syncthreads();

    int j = tid;
    float acc[32];
#pragma unroll
    for (int m = 0; m < 32; m++) acc[m] = 0.f;

    for (int k4 = 0; k4 < 32; k4++) {
        float4 w = reinterpret_cast<const float4*>(fc1w + (size_t)j * 128)[k4];
#pragma unroll
        for (int m = 0; m < 32; m++) {
            float4 h = reinterpret_cast<const float4*>(&h2s[m][0])[k4];
            acc[m] += h.x * w.x; acc[m] += h.y * w.y;
            acc[m] += h.z * w.z; acc[m] += h.w * w.w;
        }
    }

    float fb = fc1b[j], w2 = fc2w[j];
    int lane = tid & 31, wid = tid >> 5;
#pragma unroll
    for (int m = 0; m < 32; m++) {
        float v = leaky(acc[m] + fb) * w2;
#pragma unroll
        for (int off = 16; off; off >>= 1)
            v += __shfl_xor_sync(0xffffffffu, v, off);
        if (lane == 0) red[m][wid] = v;
    }
    __syncthreads();

    if (tid < 32 && tid < valid) {
        float s = fc2b[0];
#pragma unroll
        for (int w = 0; w < 8; w++) s += red[tid][w];
        out[base + tid] = s;
    }
}

// ---------------------------------------------------------------------------
extern "C" void kernel_launch(void* const* d_in, const int* in_sizes, int n_in,
                              void* d_out, int out_size) {
    const float* x    = (const float*)d_in[0];
    const int*   ei   = (const int*)d_in[1];   // int32 (JAX x64 disabled)
    const float* W1   = (const float*)d_in[2];
    const float* b1   = (const float*)d_in[3];
    const float* W3   = (const float*)d_in[4];
    const float* b3   = (const float*)d_in[5];
    const float* fc1w = (const float*)d_in[6];
    const float* fc1b = (const float*)d_in[7];
    const float* fc2w = (const float*)d_in[8];
    const float* fc2b = (const float*)d_in[9];
    float* out = (float*)d_out;

    int n = in_sizes[0] / 128;
    int E = in_sizes[1] / 2;
    int mt = (n + 63) / 64;

    static int smem_set = 0;
    if (!smem_set) {
        cudaFuncSetAttribute(k_wgemm1, cudaFuncAttributeMaxDynamicSharedMemorySize,
                             WS_TOTAL_BYTES);
        cudaFuncSetAttribute(k_wgemm2, cudaFuncAttributeMaxDynamicSharedMemorySize,
                             WS_TOTAL_BYTES);
        smem_set = 1;
    }

    // CSR build
    k_zero<<<(n + 255) / 256, 256>>>(n);
    k_hist<<<(E + 255) / 256, 256>>>(ei, E);
    k_scan<<<1, 1024>>>(n);
    k_scatter<<<(E + 255) / 256, 256>>>(ei, E);

    // weight prep (bf16 hi/lo split)
    k_prep_w1<<<(128 * 512 + 255) / 256, 256>>>(W1);
    k_prep_w3<<<(512 * 128 + 255) / 256, 256>>>(W3);

    // A1 = Ahat @ x -> g_buf1
    k_pull<<<(n * 32 + 255) / 256, 256>>>(x, 0, n);
    // H1 = leaky(A1@W1+b1) -> g_h1 (bf16 split)
    k_wgemm1<<<dim3(mt, 4), 256, WS_TOTAL_BYTES>>>(b1, n);
    // T2 = H1 @ W3 -> g_buf2
    k_wgemm2<<<mt, 256, WS_TOTAL_BYTES>>>(n);
    // A2 = Ahat @ T2 -> g_buf1
    k_pull<<<(n * 32 + 255) / 256, 256>>>(x, 1, n);
    // head
    k_final<<<(n + 31) / 32, 256>>>(b3, fc1w, fc1b, fc2w, fc2b, out, n);
}

// round 9
// speedup vs baseline: 1.6009x; 1.6009x over previous
#include <cuda_runtime.h>
#include <cuda_bf16.h>
#include <mma.h>

using namespace nvcuda;

#define MAXN 50000
#define MAXE 1000000
#define MT   391          // ceil(50000/128) m-tiles

typedef unsigned int u32;

// ---------------- scratch (device globals, no allocation) -------------------
__device__ __align__(16) float g_dinv[MAXN];
__device__ __align__(16) float g_buf1[MAXN * 128];   // A1, then A2
__device__ __align__(16) float g_buf2[MAXN * 128];   // T2
__device__ int g_cnt[MAXN];
__device__ int g_off[MAXN];
__device__ int g_pos[MAXN];
__device__ int g_srt[MAXE];
// pre-split bf16 weights (row-major)
__device__ __align__(16) __nv_bfloat16 g_w1hi[128 * 512], g_w1lo[128 * 512];
__device__ __align__(16) __nv_bfloat16 g_w3hi[512 * 128], g_w3lo[512 * 128];
// H1 fp32 row-major [MT*128][512]
__device__ __align__(16) float g_h1[MT * 128 * 512];

// ---------------- helpers -----------------------------------------------------
__device__ __forceinline__ float leaky(float v) { return v >= 0.f ? v : 0.01f * v; }

__device__ __forceinline__ unsigned short f2bf(float v) {
    __nv_bfloat16 h = __float2bfloat16_rn(v);
    return static_cast<__nv_bfloat16_raw>(h).x;
}
__device__ __forceinline__ float bf2f(unsigned short u) {
    __nv_bfloat16_raw r; r.x = u;
    return __bfloat162float(__nv_bfloat16(r));
}
__device__ __forceinline__ void bsplit(float v, unsigned short& h, unsigned short& l) {
    h = f2bf(v);
    l = f2bf(v - bf2f(h));
}

// smem strides (padded to rotate banks; keep 16B alignment)
#define SB 136            // bf16 elements per row  (272 B = 17*16)
#define SF 132            // fp32 elements per row  (528 B = 33*16)
// smem layout in bf16 elements:
#define O_AHI 0
#define O_ALO (128 * SB)
#define O_BHI (2 * 128 * SB)
#define O_BLO (3 * 128 * SB)
#define WS_TOTAL_BYTES (4 * 128 * SB * 2)    // 139264

// ---------------- CSR build (proven) ------------------------------------------
__global__ void k_zero(int n) {
    int i = blockIdx.x * blockDim.x + threadIdx.x;
    if (i < n) g_cnt[i] = 0;
}
__global__ void k_hist(const int* __restrict__ ei, int E) {
    int i = blockIdx.x * blockDim.x + threadIdx.x;
    if (i < E) atomicAdd(&g_cnt[ei[E + i]], 1);
}
__global__ void __launch_bounds__(1024) k_scan(int n) {
    __shared__ int tmp[1024];
    int tid = threadIdx.x;
    int chunk = (n + 1023) >> 10;
    int start = tid * chunk;
    int end = start + chunk; if (end > n) end = n;
    int s = 0;
    for (int i = start; i < end; i++) s += g_cnt[i];
    tmp[tid] = s;
    __syncthreads();
    for (int off = 1; off < 1024; off <<= 1) {
        int v = (tid >= off) ? tmp[tid - off] : 0;
        __syncthreads();
        tmp[tid] += v;
        __syncthreads();
    }
    int base = tmp[tid] - s;
    for (int i = start; i < end; i++) {
        g_off[i] = base; g_pos[i] = base;
        base += g_cnt[i];
        g_dinv[i] = rsqrtf((float)(g_cnt[i] + 1));
    }
}
__global__ void k_scatter(const int* __restrict__ ei, int E) {
    int i = blockIdx.x * blockDim.x + threadIdx.x;
    if (i >= E) return;
    int d = ei[E + i];
    int p = atomicAdd(&g_pos[d], 1);
    g_srt[p] = ei[i];
}

// ---------------- pull aggregation (proven) ------------------------------------
__global__ void __launch_bounds__(256) k_pull(const float* __restrict__ xin,
                                              int pass, int n) {
    int node = (blockIdx.x * blockDim.x + threadIdx.x) >> 5;
    int lane = threadIdx.x & 31;
    if (node >= n) return;
    const float* in = pass ? g_buf2 : xin;
    int off = g_off[node], cnt = g_cnt[node];
    float dd = g_dinv[node];

    float4 v = reinterpret_cast<const float4*>(in + (size_t)node * 128)[lane];
    float4 acc;
    acc.x = dd * v.x; acc.y = dd * v.y; acc.z = dd * v.z; acc.w = dd * v.w;

    int j = 0;
    for (; j + 3 < cnt; j += 4) {
        int s0 = g_srt[off + j],     s1 = g_srt[off + j + 1];
        int s2 = g_srt[off + j + 2], s3 = g_srt[off + j + 3];
        float w0 = g_dinv[s0], w1 = g_dinv[s1];
        float w2 = g_dinv[s2], w3 = g_dinv[s3];
        float4 a = reinterpret_cast<const float4*>(in + (size_t)s0 * 128)[lane];
        float4 b = reinterpret_cast<const float4*>(in + (size_t)s1 * 128)[lane];
        float4 c = reinterpret_cast<const float4*>(in + (size_t)s2 * 128)[lane];
        float4 e = reinterpret_cast<const float4*>(in + (size_t)s3 * 128)[lane];
        acc.x += w0 * a.x + w1 * b.x + w2 * c.x + w3 * e.x;
        acc.y += w0 * a.y + w1 * b.y + w2 * c.y + w3 * e.y;
        acc.z += w0 * a.z + w1 * b.z + w2 * c.z + w3 * e.z;
        acc.w += w0 * a.w + w1 * b.w + w2 * c.w + w3 * e.w;
    }
    for (; j < cnt; j++) {
        int s0 = g_srt[off + j];
        float w0 = g_dinv[s0];
        float4 a = reinterpret_cast<const float4*>(in + (size_t)s0 * 128)[lane];
        acc.x += w0 * a.x; acc.y += w0 * a.y; acc.z += w0 * a.z; acc.w += w0 * a.w;
    }
    acc.x *= dd; acc.y *= dd; acc.z *= dd; acc.w *= dd;
    reinterpret_cast<float4*>(g_buf1 + (size_t)node * 128)[lane] = acc;
}

// ---------------- weight prep: bf16 hi/lo split (row-major) --------------------
__global__ void k_prep_w1(const float* __restrict__ W1) {
    int idx = blockIdx.x * blockDim.x + threadIdx.x;
    if (idx >= 128 * 512) return;
    unsigned short h, l;
    bsplit(W1[idx], h, l);
    ((unsigned short*)g_w1hi)[idx] = h;
    ((unsigned short*)g_w1lo)[idx] = l;
}
__global__ void k_prep_w3(const float* __restrict__ W3) {
    int idx = blockIdx.x * blockDim.x + threadIdx.x;
    if (idx >= 512 * 128) return;
    unsigned short h, l;
    bsplit(W3[idx], h, l);
    ((unsigned short*)g_w3hi)[idx] = h;
    ((unsigned short*)g_w3lo)[idx] = l;
}

// ---------------- shared mainloop macro-ish helpers ----------------------------
// warp tile 32x64: acc[2][4]; block tile 128x128; 8 warps = 4m x 2n

// ---------------- GEMM1: H1 = leaky(A1 @ W1 + b1) -> fp32 ---------------------
// grid (MT, 4); block 256
__global__ void __launch_bounds__(256) k_wgemm1(const float* __restrict__ b1, int n) {
    extern __shared__ __nv_bfloat16 sh[];
    __nv_bfloat16* s_ahi = sh + O_AHI;
    __nv_bfloat16* s_alo = sh + O_ALO;
    __nv_bfloat16* s_bhi = sh + O_BHI;
    __nv_bfloat16* s_blo = sh + O_BLO;

    int tid = threadIdx.x;
    int wid = tid >> 5;
    int base = blockIdx.x * 128;
    int ns = blockIdx.y;            // n-slice 0..3 -> cols ns*128..+127 of 512

    // A tile: split fp32 -> bf16 hi/lo, padded stride
    for (int it = tid; it < 128 * 32; it += 256) {
        int r = it >> 5, c4 = (it & 31) << 2;
        float4 v = make_float4(0.f, 0.f, 0.f, 0.f);
        if (base + r < n)
            v = reinterpret_cast<const float4*>(g_buf1 + (size_t)(base + r) * 128)[it & 31];
        ushort4 h, l;
        bsplit(v.x, h.x, l.x); bsplit(v.y, h.y, l.y);
        bsplit(v.z, h.z, l.z); bsplit(v.w, h.w, l.w);
        *reinterpret_cast<ushort4*>(s_ahi + r * SB + c4) = h;
        *reinterpret_cast<ushort4*>(s_alo + r * SB + c4) = l;
    }
    // B tile: copy pre-split W1 slice [128k][128n]
    for (int it = tid; it < 128 * 16; it += 256) {
        int r = it >> 4, c8 = (it & 15) << 3;
        *reinterpret_cast<uint4*>(s_bhi + r * SB + c8) =
            *reinterpret_cast<const uint4*>(g_w1hi + r * 512 + ns * 128 + c8);
        *reinterpret_cast<uint4*>(s_blo + r * SB + c8) =
            *reinterpret_cast<const uint4*>(g_w1lo + r * 512 + ns * 128 + c8);
    }
    __syncthreads();

    int wm = wid & 3;       // rows wm*32
    int wn = wid >> 2;      // cols wn*64
    wmma::fragment<wmma::accumulator, 16, 16, 16, float> acc[2][4];
#pragma unroll
    for (int mi = 0; mi < 2; mi++)
#pragma unroll
        for (int j = 0; j < 4; j++) wmma::fill_fragment(acc[mi][j], 0.f);

#pragma unroll
    for (int ks = 0; ks < 8; ks++) {
        wmma::fragment<wmma::matrix_a, 16, 16, 16, __nv_bfloat16, wmma::row_major> ahi[2], alo[2];
#pragma unroll
        for (int mi = 0; mi < 2; mi++) {
            wmma::load_matrix_sync(ahi[mi], s_ahi + (wm * 32 + mi * 16) * SB + ks * 16, SB);
            wmma::load_matrix_sync(alo[mi], s_alo + (wm * 32 + mi * 16) * SB + ks * 16, SB);
        }
#pragma unroll
        for (int j = 0; j < 4; j++) {
            wmma::fragment<wmma::matrix_b, 16, 16, 16, __nv_bfloat16, wmma::row_major> bhi, blo;
            int col = wn * 64 + j * 16;
            wmma::load_matrix_sync(bhi, s_bhi + (ks * 16) * SB + col, SB);
            wmma::load_matrix_sync(blo, s_blo + (ks * 16) * SB + col, SB);
#pragma unroll
            for (int mi = 0; mi < 2; mi++) {
                wmma::mma_sync(acc[mi][j], ahi[mi], bhi, acc[mi][j]);
                wmma::mma_sync(acc[mi][j], alo[mi], bhi, acc[mi][j]);
                wmma::mma_sync(acc[mi][j], ahi[mi], blo, acc[mi][j]);
            }
        }
    }
    __syncthreads();   // done with smem tiles; reuse as fp32 epilogue [128][SF]

    float* e = reinterpret_cast<float*>(sh);
#pragma unroll
    for (int mi = 0; mi < 2; mi++)
#pragma unroll
        for (int j = 0; j < 4; j++)
            wmma::store_matrix_sync(e + (wm * 32 + mi * 16) * SF + wn * 64 + j * 16,
                                    acc[mi][j], SF, wmma::mem_row_major);
    __syncthreads();

    // bias + leaky -> fp32 H1 (row-major [.][512])
    for (int it = tid; it < 128 * 32; it += 256) {
        int r = it >> 5, c4 = (it & 31) << 2;
        if (base + r >= n) continue;
        float4 v = *reinterpret_cast<float4*>(e + r * SF + c4);
        float4 bb = *reinterpret_cast<const float4*>(b1 + ns * 128 + c4);
        v.x = leaky(v.x + bb.x); v.y = leaky(v.y + bb.y);
        v.z = leaky(v.z + bb.z); v.w = leaky(v.w + bb.w);
        *reinterpret_cast<float4*>(g_h1 + (size_t)(base + r) * 512 + ns * 128 + c4) = v;
    }
}

// ---------------- GEMM2: T2 = H1 @ W3 -> fp32 ---------------------------------
// grid (MT); block 256; K=512 in 4 chunks of 128
__global__ void __launch_bounds__(256) k_wgemm2(int n) {
    extern __shared__ __nv_bfloat16 sh[];
    __nv_bfloat16* s_ahi = sh + O_AHI;
    __nv_bfloat16* s_alo = sh + O_ALO;
    __nv_bfloat16* s_bhi = sh + O_BHI;
    __nv_bfloat16* s_blo = sh + O_BLO;

    int tid = threadIdx.x;
    int wid = tid >> 5;
    int base = blockIdx.x * 128;
    int wm = wid & 3;
    int wn = wid >> 2;

    wmma::fragment<wmma::accumulator, 16, 16, 16, float> acc[2][4];
#pragma unroll
    for (int mi = 0; mi < 2; mi++)
#pragma unroll
        for (int j = 0; j < 4; j++) wmma::fill_fragment(acc[mi][j], 0.f);

    for (int kc = 0; kc < 4; kc++) {
        // A chunk: H1 fp32 rows base..+127, cols kc*128..+127 -> split
        for (int it = tid; it < 128 * 32; it += 256) {
            int r = it >> 5, c4 = (it & 31) << 2;
            float4 v = make_float4(0.f, 0.f, 0.f, 0.f);
            if (base + r < n)
                v = *reinterpret_cast<const float4*>(
                        g_h1 + (size_t)(base + r) * 512 + kc * 128 + c4);
            ushort4 h, l;
            bsplit(v.x, h.x, l.x); bsplit(v.y, h.y, l.y);
            bsplit(v.z, h.z, l.z); bsplit(v.w, h.w, l.w);
            *reinterpret_cast<ushort4*>(s_ahi + r * SB + c4) = h;
            *reinterpret_cast<ushort4*>(s_alo + r * SB + c4) = l;
        }
        // B chunk: W3 rows kc*128..+127, all 128 cols
        for (int it = tid; it < 128 * 16; it += 256) {
            int r = it >> 4, c8 = (it & 15) << 3;
            *reinterpret_cast<uint4*>(s_bhi + r * SB + c8) =
                *reinterpret_cast<const uint4*>(g_w3hi + (kc * 128 + r) * 128 + c8);
            *reinterpret_cast<uint4*>(s_blo + r * SB + c8) =
                *reinterpret_cast<const uint4*>(g_w3lo + (kc * 128 + r) * 128 + c8);
        }
        __syncthreads();

#pragma unroll
        for (int ks = 0; ks < 8; ks++) {
            wmma::fragment<wmma::matrix_a, 16, 16, 16, __nv_bfloat16, wmma::row_major> ahi[2], alo[2];
#pragma unroll
            for (int mi = 0; mi < 2; mi++) {
                wmma::load_matrix_sync(ahi[mi], s_ahi + (wm * 32 + mi * 16) * SB + ks * 16, SB);
                wmma::load_matrix_sync(alo[mi], s_alo + (wm * 32 + mi * 16) * SB + ks * 16, SB);
            }
#pragma unroll
            for (int j = 0; j < 4; j++) {
                wmma::fragment<wmma::matrix_b, 16, 16, 16, __nv_bfloat16, wmma::row_major> bhi, blo;
                int col = wn * 64 + j * 16;
                wmma::load_matrix_sync(bhi, s_bhi + (ks * 16) * SB + col, SB);
                wmma::load_matrix_sync(blo, s_blo + (ks * 16) * SB + col, SB);
#pragma unroll
                for (int mi = 0; mi < 2; mi++) {
                    wmma::mma_sync(acc[mi][j], ahi[mi], bhi, acc[mi][j]);
                    wmma::mma_sync(acc[mi][j], alo[mi], bhi, acc[mi][j]);
                    wmma::mma_sync(acc[mi][j], ahi[mi], blo, acc[mi][j]);
                }
            }
        }
        __syncthreads();
    }

    float* e = reinterpret_cast<float*>(sh);
#pragma unroll
    for (int mi = 0; mi < 2; mi++)
#pragma unroll
        for (int j = 0; j < 4; j++)
            wmma::store_matrix_sync(e + (wm * 32 + mi * 16) * SF + wn * 64 + j * 16,
                                    acc[mi][j], SF, wmma::mem_row_major);
    __syncthreads();

    for (int it = tid; it < 128 * 32; it += 256) {
        int r = it >> 5, c4 = (it & 31) << 2;
        if (base + r >= n) continue;
        float4 v = *reinterpret_cast<float4*>(e + r * SF + c4);
        *reinterpret_cast<float4*>(g_buf2 + (size_t)(base + r) * 128 + c4) = v;
    }
}

// ---------------- head (proven scalar version) ---------------------------------
__global__ void __launch_bounds__(256) k_final(
    const float* __restrict__ b3,
    const float* __restrict__ fc1w, const float* __restrict__ fc1b,
    const float* __restrict__ fc2w, const float* __restrict__ fc2b,
    float* __restrict__ out, int n) {
    __shared__ float h2s[32][128];
    __shared__ float red[32][8];

    int tid = threadIdx.x;
    int base = blockIdx.x * 32;
    int valid = n - base; if (valid > 32) valid = 32;

    for (int idx = tid; idx < 32 * 32; idx += 256) {
        int m = idx >> 5, c = idx & 31;
        float4 v = make_float4(0.f, 0.f, 0.f, 0.f);
        if (m < valid)
            v = reinterpret_cast<const float4*>(g_buf1 + (size_t)(base + m) * 128)[c];
        float4 bb = reinterpret_cast<const float4*>(b3)[c];
        v.x = leaky(v.x + bb.x); v.y = leaky(v.y + bb.y);
        v.z = leaky(v.z + bb.z); v.w = leaky(v.w + bb.w);
        reinterpret_cast<float4*>(&h2s[m][0])[c] = v;
    }
    __syncthreads();

    int j = tid;
    float acc[32];
#pragma unroll
    for (int m = 0; m < 32; m++) acc[m] = 0.f;

    for (int k4 = 0; k4 < 32; k4++) {
        float4 w = reinterpret_cast<const float4*>(fc1w + (size_t)j * 128)[k4];
#pragma unroll
        for (int m = 0; m < 32; m++) {
            float4 h = reinterpret_cast<const float4*>(&h2s[m][0])[k4];
            acc[m] += h.x * w.x; acc[m] += h.y * w.y;
            acc[m] += h.z * w.z; acc[m] += h.w * w.w;
        }
    }

    float fb = fc1b[j], w2 = fc2w[j];
    int lane = tid & 31, wid = tid >> 5;
#pragma unroll
    for (int m = 0; m < 32; m++) {
        float v = leaky(acc[m] + fb) * w2;
#pragma unroll
        for (int off = 16; off; off >>= 1)
            v += __shfl_xor_sync(0xffffffffu, v, off);
        if (lane == 0) red[m][wid] = v;
    }
    __syncthreads();

    if (tid < 32 && tid < valid) {
        float s = fc2b[0];
#pragma unroll
        for (int w = 0; w < 8; w++) s += red[tid][w];
        out[base + tid] = s;
    }
}

// ---------------------------------------------------------------------------
extern "C" void kernel_launch(void* const* d_in, const int* in_sizes, int n_in,
                              void* d_out, int out_size) {
    const float* x    = (const float*)d_in[0];
    const int*   ei   = (const int*)d_in[1];   // int32 (JAX x64 disabled)
    const float* W1   = (const float*)d_in[2];
    const float* b1   = (const float*)d_in[3];
    const float* W3   = (const float*)d_in[4];
    const float* b3   = (const float*)d_in[5];
    const float* fc1w = (const float*)d_in[6];
    const float* fc1b = (const float*)d_in[7];
    const float* fc2w = (const float*)d_in[8];
    const float* fc2b = (const float*)d_in[9];
    float* out = (float*)d_out;

    int n = in_sizes[0] / 128;
    int E = in_sizes[1] / 2;
    int mt = (n + 127) / 128;

    static int smem_set = 0;
    if (!smem_set) {
        cudaFuncSetAttribute(k_wgemm1, cudaFuncAttributeMaxDynamicSharedMemorySize,
                             WS_TOTAL_BYTES);
        cudaFuncSetAttribute(k_wgemm2, cudaFuncAttributeMaxDynamicSharedMemorySize,
                             WS_TOTAL_BYTES);
        smem_set = 1;
    }

    // CSR build
    k_zero<<<(n + 255) / 256, 256>>>(n);
    k_hist<<<(E + 255) / 256, 256>>>(ei, E);
    k_scan<<<1, 1024>>>(n);
    k_scatter<<<(E + 255) / 256, 256>>>(ei, E);

    // weight prep (bf16 hi/lo split)
    k_prep_w1<<<(128 * 512 + 255) / 256, 256>>>(W1);
    k_prep_w3<<<(512 * 128 + 255) / 256, 256>>>(W3);

    // A1 = Ahat @ x -> g_buf1
    k_pull<<<(n * 32 + 255) / 256, 256>>>(x, 0, n);
    // H1 = leaky(A1@W1+b1) -> g_h1 (fp32)
    k_wgemm1<<<dim3(mt, 4), 256, WS_TOTAL_BYTES>>>(b1, n);
    // T2 = H1 @ W3 -> g_buf2
    k_wgemm2<<<mt, 256, WS_TOTAL_BYTES>>>(n);
    // A2 = Ahat @ T2 -> g_buf1
    k_pull<<<(n * 32 + 255) / 256, 256>>>(x, 1, n);
    // head
    k_final<<<(n + 31) / 32, 256>>>(b3, fc1w, fc1b, fc2w, fc2b, out, n);
}

// round 10
// speedup vs baseline: 1.7722x; 1.1070x over previous
#include <cuda_runtime.h>
#include <cuda_bf16.h>
#include <mma.h>

using namespace nvcuda;

#define MAXN 50000
#define MAXE 1000000
#define MT   391          // ceil(50000/128) m-tiles

typedef unsigned int u32;

// ---------------- scratch (device globals, no allocation) -------------------
__device__ __align__(16) float g_dinv[MAXN];
__device__ __align__(16) float g_buf1[MAXN * 128];   // A1, then A2
__device__ __align__(16) float g_buf2[MAXN * 128];   // T2
__device__ int g_cnt[MAXN];
__device__ int g_off[MAXN];
__device__ int g_pos[MAXN];
__device__ int g_srt[MAXE];
// pre-split bf16 weights (row-major)
__device__ __align__(16) __nv_bfloat16 g_w1hi[128 * 512], g_w1lo[128 * 512];
__device__ __align__(16) __nv_bfloat16 g_w3hi[512 * 128], g_w3lo[512 * 128];
__device__ __align__(16) __nv_bfloat16 g_fc1hi[256 * 128], g_fc1lo[256 * 128];
// H1 fp32 row-major [MT*128][512]
__device__ __align__(16) float g_h1[MT * 128 * 512];

// ---------------- helpers -----------------------------------------------------
__device__ __forceinline__ float leaky(float v) { return v >= 0.f ? v : 0.01f * v; }

__device__ __forceinline__ unsigned short f2bf(float v) {
    __nv_bfloat16 h = __float2bfloat16_rn(v);
    return static_cast<__nv_bfloat16_raw>(h).x;
}
__device__ __forceinline__ float bf2f(unsigned short u) {
    __nv_bfloat16_raw r; r.x = u;
    return __bfloat162float(__nv_bfloat16(r));
}
__device__ __forceinline__ void bsplit(float v, unsigned short& h, unsigned short& l) {
    h = f2bf(v);
    l = f2bf(v - bf2f(h));
}

// smem strides (padded to rotate banks; keep 16B alignment)
#define SB 136            // bf16 elements per row  (272 B = 17*16)
#define SF 132            // fp32 elements per row  (528 B = 33*16)
#define O_AHI 0
#define O_ALO (128 * SB)
#define O_BHI (2 * 128 * SB)
#define O_BLO (3 * 128 * SB)
#define WS_TOTAL_BYTES (4 * 128 * SB * 2)    // 139264

// head smem: A split tiles [64][SB] x2 (bf16), reused as epilogue fp32 [64][264]
#define HF 264            // fp32 epilogue stride (1056 B = 66*16)
#define HS_TOTAL_BYTES 69632   // max(2*64*SB*2, 64*HF*4) = max(69632, 67584)

// ---------------- CSR build (proven) ------------------------------------------
__global__ void k_zero(int n) {
    int i = blockIdx.x * blockDim.x + threadIdx.x;
    if (i < n) g_cnt[i] = 0;
}
__global__ void k_hist(const int* __restrict__ ei, int E) {
    int i = blockIdx.x * blockDim.x + threadIdx.x;
    if (i < E) atomicAdd(&g_cnt[ei[E + i]], 1);
}
__global__ void __launch_bounds__(1024) k_scan(int n) {
    __shared__ int tmp[1024];
    int tid = threadIdx.x;
    int chunk = (n + 1023) >> 10;
    int start = tid * chunk;
    int end = start + chunk; if (end > n) end = n;
    int s = 0;
    for (int i = start; i < end; i++) s += g_cnt[i];
    tmp[tid] = s;
    __syncthreads();
    for (int off = 1; off < 1024; off <<= 1) {
        int v = (tid >= off) ? tmp[tid - off] : 0;
        __syncthreads();
        tmp[tid] += v;
        __syncthreads();
    }
    int base = tmp[tid] - s;
    for (int i = start; i < end; i++) {
        g_off[i] = base; g_pos[i] = base;
        base += g_cnt[i];
        g_dinv[i] = rsqrtf((float)(g_cnt[i] + 1));
    }
}
__global__ void k_scatter(const int* __restrict__ ei, int E) {
    int i = blockIdx.x * blockDim.x + threadIdx.x;
    if (i >= E) return;
    int d = ei[E + i];
    int p = atomicAdd(&g_pos[d], 1);
    g_srt[p] = ei[i];
}

// ---------------- pull aggregation (proven) ------------------------------------
__global__ void __launch_bounds__(256) k_pull(const float* __restrict__ xin,
                                              int pass, int n) {
    int node = (blockIdx.x * blockDim.x + threadIdx.x) >> 5;
    int lane = threadIdx.x & 31;
    if (node >= n) return;
    const float* in = pass ? g_buf2 : xin;
    int off = g_off[node], cnt = g_cnt[node];
    float dd = g_dinv[node];

    float4 v = reinterpret_cast<const float4*>(in + (size_t)node * 128)[lane];
    float4 acc;
    acc.x = dd * v.x; acc.y = dd * v.y; acc.z = dd * v.z; acc.w = dd * v.w;

    int j = 0;
    for (; j + 3 < cnt; j += 4) {
        int s0 = g_srt[off + j],     s1 = g_srt[off + j + 1];
        int s2 = g_srt[off + j + 2], s3 = g_srt[off + j + 3];
        float w0 = g_dinv[s0], w1 = g_dinv[s1];
        float w2 = g_dinv[s2], w3 = g_dinv[s3];
        float4 a = reinterpret_cast<const float4*>(in + (size_t)s0 * 128)[lane];
        float4 b = reinterpret_cast<const float4*>(in + (size_t)s1 * 128)[lane];
        float4 c = reinterpret_cast<const float4*>(in + (size_t)s2 * 128)[lane];
        float4 e = reinterpret_cast<const float4*>(in + (size_t)s3 * 128)[lane];
        acc.x += w0 * a.x + w1 * b.x + w2 * c.x + w3 * e.x;
        acc.y += w0 * a.y + w1 * b.y + w2 * c.y + w3 * e.y;
        acc.z += w0 * a.z + w1 * b.z + w2 * c.z + w3 * e.z;
        acc.w += w0 * a.w + w1 * b.w + w2 * c.w + w3 * e.w;
    }
    for (; j < cnt; j++) {
        int s0 = g_srt[off + j];
        float w0 = g_dinv[s0];
        float4 a = reinterpret_cast<const float4*>(in + (size_t)s0 * 128)[lane];
        acc.x += w0 * a.x; acc.y += w0 * a.y; acc.z += w0 * a.z; acc.w += w0 * a.w;
    }
    acc.x *= dd; acc.y *= dd; acc.z *= dd; acc.w *= dd;
    reinterpret_cast<float4*>(g_buf1 + (size_t)node * 128)[lane] = acc;
}

// ---------------- weight prep: bf16 hi/lo split (row-major) --------------------
__global__ void k_prep_w1(const float* __restrict__ W1) {
    int idx = blockIdx.x * blockDim.x + threadIdx.x;
    if (idx >= 128 * 512) return;
    unsigned short h, l;
    bsplit(W1[idx], h, l);
    ((unsigned short*)g_w1hi)[idx] = h;
    ((unsigned short*)g_w1lo)[idx] = l;
}
__global__ void k_prep_w3(const float* __restrict__ W3) {
    int idx = blockIdx.x * blockDim.x + threadIdx.x;
    if (idx >= 512 * 128) return;
    unsigned short h, l;
    bsplit(W3[idx], h, l);
    ((unsigned short*)g_w3hi)[idx] = h;
    ((unsigned short*)g_w3lo)[idx] = l;
}
__global__ void k_prep_fc1(const float* __restrict__ fc1w) {
    int idx = blockIdx.x * blockDim.x + threadIdx.x;
    if (idx >= 256 * 128) return;
    unsigned short h, l;
    bsplit(fc1w[idx], h, l);
    ((unsigned short*)g_fc1hi)[idx] = h;
    ((unsigned short*)g_fc1lo)[idx] = l;
}

// ---------------- GEMM1: H1 = leaky(A1 @ W1 + b1) -> fp32 ---------------------
// grid (MT, 4); block 256; block tile 128x128; 8 warps = 4m x 2n
__global__ void __launch_bounds__(256) k_wgemm1(const float* __restrict__ b1, int n) {
    extern __shared__ __nv_bfloat16 sh[];
    __nv_bfloat16* s_ahi = sh + O_AHI;
    __nv_bfloat16* s_alo = sh + O_ALO;
    __nv_bfloat16* s_bhi = sh + O_BHI;
    __nv_bfloat16* s_blo = sh + O_BLO;

    int tid = threadIdx.x;
    int wid = tid >> 5;
    int base = blockIdx.x * 128;
    int ns = blockIdx.y;

    for (int it = tid; it < 128 * 32; it += 256) {
        int r = it >> 5, c4 = (it & 31) << 2;
        float4 v = make_float4(0.f, 0.f, 0.f, 0.f);
        if (base + r < n)
            v = reinterpret_cast<const float4*>(g_buf1 + (size_t)(base + r) * 128)[it & 31];
        ushort4 h, l;
        bsplit(v.x, h.x, l.x); bsplit(v.y, h.y, l.y);
        bsplit(v.z, h.z, l.z); bsplit(v.w, h.w, l.w);
        *reinterpret_cast<ushort4*>(s_ahi + r * SB + c4) = h;
        *reinterpret_cast<ushort4*>(s_alo + r * SB + c4) = l;
    }
    for (int it = tid; it < 128 * 16; it += 256) {
        int r = it >> 4, c8 = (it & 15) << 3;
        *reinterpret_cast<uint4*>(s_bhi + r * SB + c8) =
            *reinterpret_cast<const uint4*>(g_w1hi + r * 512 + ns * 128 + c8);
        *reinterpret_cast<uint4*>(s_blo + r * SB + c8) =
            *reinterpret_cast<const uint4*>(g_w1lo + r * 512 + ns * 128 + c8);
    }
    __syncthreads();

    int wm = wid & 3;
    int wn = wid >> 2;
    wmma::fragment<wmma::accumulator, 16, 16, 16, float> acc[2][4];
#pragma unroll
    for (int mi = 0; mi < 2; mi++)
#pragma unroll
        for (int j = 0; j < 4; j++) wmma::fill_fragment(acc[mi][j], 0.f);

#pragma unroll
    for (int ks = 0; ks < 8; ks++) {
        wmma::fragment<wmma::matrix_a, 16, 16, 16, __nv_bfloat16, wmma::row_major> ahi[2], alo[2];
#pragma unroll
        for (int mi = 0; mi < 2; mi++) {
            wmma::load_matrix_sync(ahi[mi], s_ahi + (wm * 32 + mi * 16) * SB + ks * 16, SB);
            wmma::load_matrix_sync(alo[mi], s_alo + (wm * 32 + mi * 16) * SB + ks * 16, SB);
        }
#pragma unroll
        for (int j = 0; j < 4; j++) {
            wmma::fragment<wmma::matrix_b, 16, 16, 16, __nv_bfloat16, wmma::row_major> bhi, blo;
            int col = wn * 64 + j * 16;
            wmma::load_matrix_sync(bhi, s_bhi + (ks * 16) * SB + col, SB);
            wmma::load_matrix_sync(blo, s_blo + (ks * 16) * SB + col, SB);
#pragma unroll
            for (int mi = 0; mi < 2; mi++) {
                wmma::mma_sync(acc[mi][j], ahi[mi], bhi, acc[mi][j]);
                wmma::mma_sync(acc[mi][j], alo[mi], bhi, acc[mi][j]);
                wmma::mma_sync(acc[mi][j], ahi[mi], blo, acc[mi][j]);
            }
        }
    }
    __syncthreads();

    float* e = reinterpret_cast<float*>(sh);
#pragma unroll
    for (int mi = 0; mi < 2; mi++)
#pragma unroll
        for (int j = 0; j < 4; j++)
            wmma::store_matrix_sync(e + (wm * 32 + mi * 16) * SF + wn * 64 + j * 16,
                                    acc[mi][j], SF, wmma::mem_row_major);
    __syncthreads();

    for (int it = tid; it < 128 * 32; it += 256) {
        int r = it >> 5, c4 = (it & 31) << 2;
        if (base + r >= n) continue;
        float4 v = *reinterpret_cast<float4*>(e + r * SF + c4);
        float4 bb = *reinterpret_cast<const float4*>(b1 + ns * 128 + c4);
        v.x = leaky(v.x + bb.x); v.y = leaky(v.y + bb.y);
        v.z = leaky(v.z + bb.z); v.w = leaky(v.w + bb.w);
        *reinterpret_cast<float4*>(g_h1 + (size_t)(base + r) * 512 + ns * 128 + c4) = v;
    }
}

// ---------------- GEMM2: T2 = H1 @ W3 -> fp32 ---------------------------------
__global__ void __launch_bounds__(256) k_wgemm2(int n) {
    extern __shared__ __nv_bfloat16 sh[];
    __nv_bfloat16* s_ahi = sh + O_AHI;
    __nv_bfloat16* s_alo = sh + O_ALO;
    __nv_bfloat16* s_bhi = sh + O_BHI;
    __nv_bfloat16* s_blo = sh + O_BLO;

    int tid = threadIdx.x;
    int wid = tid >> 5;
    int base = blockIdx.x * 128;
    int wm = wid & 3;
    int wn = wid >> 2;

    wmma::fragment<wmma::accumulator, 16, 16, 16, float> acc[2][4];
#pragma unroll
    for (int mi = 0; mi < 2; mi++)
#pragma unroll
        for (int j = 0; j < 4; j++) wmma::fill_fragment(acc[mi][j], 0.f);

    for (int kc = 0; kc < 4; kc++) {
        for (int it = tid; it < 128 * 32; it += 256) {
            int r = it >> 5, c4 = (it & 31) << 2;
            float4 v = make_float4(0.f, 0.f, 0.f, 0.f);
            if (base + r < n)
                v = *reinterpret_cast<const float4*>(
                        g_h1 + (size_t)(base + r) * 512 + kc * 128 + c4);
            ushort4 h, l;
            bsplit(v.x, h.x, l.x); bsplit(v.y, h.y, l.y);
            bsplit(v.z, h.z, l.z); bsplit(v.w, h.w, l.w);
            *reinterpret_cast<ushort4*>(s_ahi + r * SB + c4) = h;
            *reinterpret_cast<ushort4*>(s_alo + r * SB + c4) = l;
        }
        for (int it = tid; it < 128 * 16; it += 256) {
            int r = it >> 4, c8 = (it & 15) << 3;
            *reinterpret_cast<uint4*>(s_bhi + r * SB + c8) =
                *reinterpret_cast<const uint4*>(g_w3hi + (kc * 128 + r) * 128 + c8);
            *reinterpret_cast<uint4*>(s_blo + r * SB + c8) =
                *reinterpret_cast<const uint4*>(g_w3lo + (kc * 128 + r) * 128 + c8);
        }
        __syncthreads();

#pragma unroll
        for (int ks = 0; ks < 8; ks++) {
            wmma::fragment<wmma::matrix_a, 16, 16, 16, __nv_bfloat16, wmma::row_major> ahi[2], alo[2];
#pragma unroll
            for (int mi = 0; mi < 2; mi++) {
                wmma::load_matrix_sync(ahi[mi], s_ahi + (wm * 32 + mi * 16) * SB + ks * 16, SB);
                wmma::load_matrix_sync(alo[mi], s_alo + (wm * 32 + mi * 16) * SB + ks * 16, SB);
            }
#pragma unroll
            for (int j = 0; j < 4; j++) {
                wmma::fragment<wmma::matrix_b, 16, 16, 16, __nv_bfloat16, wmma::row_major> bhi, blo;
                int col = wn * 64 + j * 16;
                wmma::load_matrix_sync(bhi, s_bhi + (ks * 16) * SB + col, SB);
                wmma::load_matrix_sync(blo, s_blo + (ks * 16) * SB + col, SB);
#pragma unroll
                for (int mi = 0; mi < 2; mi++) {
                    wmma::mma_sync(acc[mi][j], ahi[mi], bhi, acc[mi][j]);
                    wmma::mma_sync(acc[mi][j], alo[mi], bhi, acc[mi][j]);
                    wmma::mma_sync(acc[mi][j], ahi[mi], blo, acc[mi][j]);
                }
            }
        }
        __syncthreads();
    }

    float* e = reinterpret_cast<float*>(sh);
#pragma unroll
    for (int mi = 0; mi < 2; mi++)
#pragma unroll
        for (int j = 0; j < 4; j++)
            wmma::store_matrix_sync(e + (wm * 32 + mi * 16) * SF + wn * 64 + j * 16,
                                    acc[mi][j], SF, wmma::mem_row_major);
    __syncthreads();

    for (int it = tid; it < 128 * 32; it += 256) {
        int r = it >> 5, c4 = (it & 31) << 2;
        if (base + r >= n) continue;
        float4 v = *reinterpret_cast<float4*>(e + r * SF + c4);
        *reinterpret_cast<float4*>(g_buf2 + (size_t)(base + r) * 128 + c4) = v;
    }
}

// ---------------- head: leaky(A2+b3) -> FC1(wmma) + leaky -> FC2 --------------
// grid ceil(n/64); block 256 = 8 warps (2m x 4n); warp tile 32 rows x 64 ch
__global__ void __launch_bounds__(256) k_final(
    const float* __restrict__ b3, const float* __restrict__ fc1b,
    const float* __restrict__ fc2w, const float* __restrict__ fc2b,
    float* __restrict__ out, int n) {
    extern __shared__ __nv_bfloat16 sh[];
    __nv_bfloat16* s_ahi = sh;
    __nv_bfloat16* s_alo = sh + 64 * SB;

    int tid = threadIdx.x;
    int wid = tid >> 5;
    int base = blockIdx.x * 64;

    // A2 tile: bias+leaky, split -> smem
    for (int it = tid; it < 64 * 32; it += 256) {
        int r = it >> 5, c4 = (it & 31) << 2;
        float4 v = make_float4(0.f, 0.f, 0.f, 0.f);
        if (base + r < n)
            v = reinterpret_cast<const float4*>(g_buf1 + (size_t)(base + r) * 128)[it & 31];
        float4 bb = *reinterpret_cast<const float4*>(b3 + c4);
        v.x = leaky(v.x + bb.x); v.y = leaky(v.y + bb.y);
        v.z = leaky(v.z + bb.z); v.w = leaky(v.w + bb.w);
        ushort4 h, l;
        bsplit(v.x, h.x, l.x); bsplit(v.y, h.y, l.y);
        bsplit(v.z, h.z, l.z); bsplit(v.w, h.w, l.w);
        *reinterpret_cast<ushort4*>(s_ahi + r * SB + c4) = h;
        *reinterpret_cast<ushort4*>(s_alo + r * SB + c4) = l;
    }
    __syncthreads();

    int wm = wid & 1;       // rows wm*32
    int wn = wid >> 1;      // ch cols wn*64
    wmma::fragment<wmma::accumulator, 16, 16, 16, float> acc[2][4];
#pragma unroll
    for (int mi = 0; mi < 2; mi++)
#pragma unroll
        for (int j = 0; j < 4; j++) wmma::fill_fragment(acc[mi][j], 0.f);

#pragma unroll
    for (int ks = 0; ks < 8; ks++) {
        wmma::fragment<wmma::matrix_a, 16, 16, 16, __nv_bfloat16, wmma::row_major> ahi[2], alo[2];
#pragma unroll
        for (int mi = 0; mi < 2; mi++) {
            wmma::load_matrix_sync(ahi[mi], s_ahi + (wm * 32 + mi * 16) * SB + ks * 16, SB);
            wmma::load_matrix_sync(alo[mi], s_alo + (wm * 32 + mi * 16) * SB + ks * 16, SB);
        }
#pragma unroll
        for (int j = 0; j < 4; j++) {
            // B col-major from gmem: element (k, ch) at fc1*[ch*128 + k]
            int col = wn * 64 + j * 16;
            wmma::fragment<wmma::matrix_b, 16, 16, 16, __nv_bfloat16, wmma::col_major> bhi, blo;
            wmma::load_matrix_sync(bhi, g_fc1hi + (size_t)col * 128 + ks * 16, 128);
            wmma::load_matrix_sync(blo, g_fc1lo + (size_t)col * 128 + ks * 16, 128);
#pragma unroll
            for (int mi = 0; mi < 2; mi++) {
                wmma::mma_sync(acc[mi][j], ahi[mi], bhi, acc[mi][j]);
                wmma::mma_sync(acc[mi][j], alo[mi], bhi, acc[mi][j]);
                wmma::mma_sync(acc[mi][j], ahi[mi], blo, acc[mi][j]);
            }
        }
    }
    __syncthreads();   // reuse smem as fp32 epilogue [64][HF]

    float* e = reinterpret_cast<float*>(sh);
#pragma unroll
    for (int mi = 0; mi < 2; mi++)
#pragma unroll
        for (int j = 0; j < 4; j++)
            wmma::store_matrix_sync(e + (wm * 32 + mi * 16) * HF + wn * 64 + j * 16,
                                    acc[mi][j], HF, wmma::mem_row_major);
    __syncthreads();

    // FC1 bias + leaky + FC2 dot: 4 threads per node, 64 channels each
    {
        int node = tid >> 2;        // 0..63
        int part = tid & 3;         // 0..3 -> channels part*64..+63
        float s = 0.f;
        const float* er = e + node * HF + part * 64;
#pragma unroll
        for (int c4 = 0; c4 < 16; c4++) {
            float4 v = *reinterpret_cast<const float4*>(er + c4 * 4);
            float4 fb = *reinterpret_cast<const float4*>(fc1b + part * 64 + c4 * 4);
            float4 w2 = *reinterpret_cast<const float4*>(fc2w + part * 64 + c4 * 4);
            s += leaky(v.x + fb.x) * w2.x + leaky(v.y + fb.y) * w2.y
               + leaky(v.z + fb.z) * w2.z + leaky(v.w + fb.w) * w2.w;
        }
        s += __shfl_xor_sync(0xffffffffu, s, 1);
        s += __shfl_xor_sync(0xffffffffu, s, 2);
        if (part == 0 && base + node < n)
            out[base + node] = s + fc2b[0];
    }
}

// ---------------------------------------------------------------------------
extern "C" void kernel_launch(void* const* d_in, const int* in_sizes, int n_in,
                              void* d_out, int out_size) {
    const float* x    = (const float*)d_in[0];
    const int*   ei   = (const int*)d_in[1];   // int32 (JAX x64 disabled)
    const float* W1   = (const float*)d_in[2];
    const float* b1   = (const float*)d_in[3];
    const float* W3   = (const float*)d_in[4];
    const float* b3   = (const float*)d_in[5];
    const float* fc1w = (const float*)d_in[6];
    const float* fc1b = (const float*)d_in[7];
    const float* fc2w = (const float*)d_in[8];
    const float* fc2b = (const float*)d_in[9];
    float* out = (float*)d_out;

    int n = in_sizes[0] / 128;
    int E = in_sizes[1] / 2;
    int mt = (n + 127) / 128;
    int mt64 = (n + 63) / 64;

    static int smem_set = 0;
    if (!smem_set) {
        cudaFuncSetAttribute(k_wgemm1, cudaFuncAttributeMaxDynamicSharedMemorySize,
                             WS_TOTAL_BYTES);
        cudaFuncSetAttribute(k_wgemm2, cudaFuncAttributeMaxDynamicSharedMemorySize,
                             WS_TOTAL_BYTES);
        cudaFuncSetAttribute(k_final, cudaFuncAttributeMaxDynamicSharedMemorySize,
                             HS_TOTAL_BYTES);
        smem_set = 1;
    }

    // CSR build
    k_zero<<<(n + 255) / 256, 256>>>(n);
    k_hist<<<(E + 255) / 256, 256>>>(ei, E);
    k_scan<<<1, 1024>>>(n);
    k_scatter<<<(E + 255) / 256, 256>>>(ei, E);

    // weight prep (bf16 hi/lo split)
    k_prep_w1<<<(128 * 512 + 255) / 256, 256>>>(W1);
    k_prep_w3<<<(512 * 128 + 255) / 256, 256>>>(W3);
    k_prep_fc1<<<(256 * 128 + 255) / 256, 256>>>(fc1w);

    // A1 = Ahat @ x -> g_buf1
    k_pull<<<(n * 32 + 255) / 256, 256>>>(x, 0, n);
    // H1 = leaky(A1@W1+b1) -> g_h1 (fp32)
    k_wgemm1<<<dim3(mt, 4), 256, WS_TOTAL_BYTES>>>(b1, n);
    // T2 = H1 @ W3 -> g_buf2
    k_wgemm2<<<mt, 256, WS_TOTAL_BYTES>>>(n);
    // A2 = Ahat @ T2 -> g_buf1
    k_pull<<<(n * 32 + 255) / 256, 256>>>(x, 1, n);
    // head
    k_final<<<mt64, 256, HS_TOTAL_BYTES>>>(b3, fc1b, fc2w, fc2b, out, n);
}

// round 11
// speedup vs baseline: 2.0978x; 1.1837x over previous
#include <cuda_runtime.h>
#include <cuda_bf16.h>
#include <mma.h>

using namespace nvcuda;

#define MAXN 50000
#define MAXE 1000000
#define MT   391          // ceil(50000/128) m-tiles

typedef unsigned int u32;

// ---------------- scratch (device globals, no allocation) -------------------
__device__ __align__(16) float g_dinv[MAXN];
__device__ __align__(16) float g_buf1[MAXN * 128];   // A1
__device__ __align__(16) float g_buf2[MAXN * 128];   // T2
__device__ int g_cnt[MAXN];
__device__ int g_off[MAXN];
__device__ int g_pos[MAXN];
__device__ int g_srt[MAXE];
// pre-split bf16 weights (row-major)
__device__ __align__(16) __nv_bfloat16 g_w1hi[128 * 512], g_w1lo[128 * 512];
__device__ __align__(16) __nv_bfloat16 g_w3hi[512 * 128], g_w3lo[512 * 128];
__device__ __align__(16) __nv_bfloat16 g_fc1hi[256 * 128], g_fc1lo[256 * 128];

// ---------------- helpers -----------------------------------------------------
__device__ __forceinline__ float leaky(float v) { return v >= 0.f ? v : 0.01f * v; }

__device__ __forceinline__ unsigned short f2bf(float v) {
    __nv_bfloat16 h = __float2bfloat16_rn(v);
    return static_cast<__nv_bfloat16_raw>(h).x;
}
__device__ __forceinline__ float bf2f(unsigned short u) {
    __nv_bfloat16_raw r; r.x = u;
    return __bfloat162float(__nv_bfloat16(r));
}
__device__ __forceinline__ void bsplit(float v, unsigned short& h, unsigned short& l) {
    h = f2bf(v);
    l = f2bf(v - bf2f(h));
}

// smem strides (padded to rotate banks; keep 16B alignment)
#define SB 136            // bf16 elements per row  (272 B = 17*16)
#define SF 132            // fp32 elements per row  (528 B = 33*16)
// fused gemm smem: 6 regions of 128*SB bf16
#define O_AHI 0
#define O_ALO (128 * SB)
#define O_BHI (2 * 128 * SB)
#define O_BLO (3 * 128 * SB)
#define O_HHI (4 * 128 * SB)
#define O_HLO (5 * 128 * SB)
#define WG_TOTAL_BYTES (6 * 128 * SB * 2)   // 208896

// head smem: A split tiles [64][SB] x2 (bf16), reused as epilogue fp32 [64][264]
#define HF 264
#define HS_TOTAL_BYTES 69632

// ---------------- CSR build (proven) ------------------------------------------
__global__ void k_zero(int n) {
    int i = blockIdx.x * blockDim.x + threadIdx.x;
    if (i < n) g_cnt[i] = 0;
}
__global__ void k_hist(const int* __restrict__ ei, int E) {
    int i = blockIdx.x * blockDim.x + threadIdx.x;
    if (i < E) atomicAdd(&g_cnt[ei[E + i]], 1);
}
__global__ void __launch_bounds__(1024) k_scan(int n) {
    __shared__ int tmp[1024];
    int tid = threadIdx.x;
    int chunk = (n + 1023) >> 10;
    int start = tid * chunk;
    int end = start + chunk; if (end > n) end = n;
    int s = 0;
    for (int i = start; i < end; i++) s += g_cnt[i];
    tmp[tid] = s;
    __syncthreads();
    for (int off = 1; off < 1024; off <<= 1) {
        int v = (tid >= off) ? tmp[tid - off] : 0;
        __syncthreads();
        tmp[tid] += v;
        __syncthreads();
    }
    int base = tmp[tid] - s;
    for (int i = start; i < end; i++) {
        g_off[i] = base; g_pos[i] = base;
        base += g_cnt[i];
        g_dinv[i] = rsqrtf((float)(g_cnt[i] + 1));
    }
}
__global__ void k_scatter(const int* __restrict__ ei, int E) {
    int i = blockIdx.x * blockDim.x + threadIdx.x;
    if (i >= E) return;
    int d = ei[E + i];
    int p = atomicAdd(&g_pos[d], 1);
    g_srt[p] = ei[i];
}

// ---------------- pull aggregation pass 1 (proven) -----------------------------
__global__ void __launch_bounds__(256) k_pull(const float* __restrict__ xin, int n) {
    int node = (blockIdx.x * blockDim.x + threadIdx.x) >> 5;
    int lane = threadIdx.x & 31;
    if (node >= n) return;
    const float* in = xin;
    int off = g_off[node], cnt = g_cnt[node];
    float dd = g_dinv[node];

    float4 v = reinterpret_cast<const float4*>(in + (size_t)node * 128)[lane];
    float4 acc;
    acc.x = dd * v.x; acc.y = dd * v.y; acc.z = dd * v.z; acc.w = dd * v.w;

    int j = 0;
    for (; j + 3 < cnt; j += 4) {
        int s0 = g_srt[off + j],     s1 = g_srt[off + j + 1];
        int s2 = g_srt[off + j + 2], s3 = g_srt[off + j + 3];
        float w0 = g_dinv[s0], w1 = g_dinv[s1];
        float w2 = g_dinv[s2], w3 = g_dinv[s3];
        float4 a = reinterpret_cast<const float4*>(in + (size_t)s0 * 128)[lane];
        float4 b = reinterpret_cast<const float4*>(in + (size_t)s1 * 128)[lane];
        float4 c = reinterpret_cast<const float4*>(in + (size_t)s2 * 128)[lane];
        float4 e = reinterpret_cast<const float4*>(in + (size_t)s3 * 128)[lane];
        acc.x += w0 * a.x + w1 * b.x + w2 * c.x + w3 * e.x;
        acc.y += w0 * a.y + w1 * b.y + w2 * c.y + w3 * e.y;
        acc.z += w0 * a.z + w1 * b.z + w2 * c.z + w3 * e.z;
        acc.w += w0 * a.w + w1 * b.w + w2 * c.w + w3 * e.w;
    }
    for (; j < cnt; j++) {
        int s0 = g_srt[off + j];
        float w0 = g_dinv[s0];
        float4 a = reinterpret_cast<const float4*>(in + (size_t)s0 * 128)[lane];
        acc.x += w0 * a.x; acc.y += w0 * a.y; acc.z += w0 * a.z; acc.w += w0 * a.w;
    }
    acc.x *= dd; acc.y *= dd; acc.z *= dd; acc.w *= dd;
    reinterpret_cast<float4*>(g_buf1 + (size_t)node * 128)[lane] = acc;
}

// ---------------- merged weight prep: bf16 hi/lo splits -------------------------
__global__ void k_prep(const float* __restrict__ W1, const float* __restrict__ W3,
                       const float* __restrict__ fc1w) {
    int idx = blockIdx.x * blockDim.x + threadIdx.x;
    unsigned short h, l;
    if (idx < 65536) {
        bsplit(W1[idx], h, l);
        ((unsigned short*)g_w1hi)[idx] = h;
        ((unsigned short*)g_w1lo)[idx] = l;
    } else if (idx < 131072) {
        int j = idx - 65536;
        bsplit(W3[j], h, l);
        ((unsigned short*)g_w3hi)[j] = h;
        ((unsigned short*)g_w3lo)[j] = l;
    } else if (idx < 163840) {
        int j = idx - 131072;
        bsplit(fc1w[j], h, l);
        ((unsigned short*)g_fc1hi)[j] = h;
        ((unsigned short*)g_fc1lo)[j] = l;
    }
}

// ---------------- fused GEMM: T2 = (leaky(A1@W1+b1)) @ W3 ---------------------
// grid (MT); block 256 = 8 warps (4m x 2n); per chunk: mainloop1 -> H chunk
// in smem -> mainloop2 accumulating T2 in registers. No H1 gmem round-trip.
__global__ void __launch_bounds__(256) k_wgemm12(const float* __restrict__ b1, int n) {
    extern __shared__ __nv_bfloat16 sh[];
    __nv_bfloat16* s_ahi = sh + O_AHI;
    __nv_bfloat16* s_alo = sh + O_ALO;
    __nv_bfloat16* s_bhi = sh + O_BHI;
    __nv_bfloat16* s_blo = sh + O_BLO;
    __nv_bfloat16* s_hhi = sh + O_HHI;
    __nv_bfloat16* s_hlo = sh + O_HLO;
    float* stg = reinterpret_cast<float*>(sh + O_BHI);   // fp32 staging [128][SF]

    int tid = threadIdx.x;
    int wid = tid >> 5;
    int base = blockIdx.x * 128;
    int wm = wid & 3;       // rows wm*32
    int wn = wid >> 2;      // cols wn*64

    // A1 tile: split fp32 -> bf16 hi/lo (lives for the whole kernel)
    for (int it = tid; it < 128 * 32; it += 256) {
        int r = it >> 5, c4 = (it & 31) << 2;
        float4 v = make_float4(0.f, 0.f, 0.f, 0.f);
        if (base + r < n)
            v = reinterpret_cast<const float4*>(g_buf1 + (size_t)(base + r) * 128)[it & 31];
        ushort4 h, l;
        bsplit(v.x, h.x, l.x); bsplit(v.y, h.y, l.y);
        bsplit(v.z, h.z, l.z); bsplit(v.w, h.w, l.w);
        *reinterpret_cast<ushort4*>(s_ahi + r * SB + c4) = h;
        *reinterpret_cast<ushort4*>(s_alo + r * SB + c4) = l;
    }

    wmma::fragment<wmma::accumulator, 16, 16, 16, float> acc2[2][4];
#pragma unroll
    for (int mi = 0; mi < 2; mi++)
#pragma unroll
        for (int j = 0; j < 4; j++) wmma::fill_fragment(acc2[mi][j], 0.f);

    for (int c = 0; c < 4; c++) {
        // load W1 slice c (B for mainloop1)
        for (int it = tid; it < 128 * 16; it += 256) {
            int r = it >> 4, c8 = (it & 15) << 3;
            *reinterpret_cast<uint4*>(s_bhi + r * SB + c8) =
                *reinterpret_cast<const uint4*>(g_w1hi + r * 512 + c * 128 + c8);
            *reinterpret_cast<uint4*>(s_blo + r * SB + c8) =
                *reinterpret_cast<const uint4*>(g_w1lo + r * 512 + c * 128 + c8);
        }
        __syncthreads();

        // mainloop1: acc1 = A1 @ W1slice
        wmma::fragment<wmma::accumulator, 16, 16, 16, float> acc1[2][4];
#pragma unroll
        for (int mi = 0; mi < 2; mi++)
#pragma unroll
            for (int j = 0; j < 4; j++) wmma::fill_fragment(acc1[mi][j], 0.f);

#pragma unroll
        for (int ks = 0; ks < 8; ks++) {
            wmma::fragment<wmma::matrix_a, 16, 16, 16, __nv_bfloat16, wmma::row_major> ahi[2], alo[2];
#pragma unroll
            for (int mi = 0; mi < 2; mi++) {
                wmma::load_matrix_sync(ahi[mi], s_ahi + (wm * 32 + mi * 16) * SB + ks * 16, SB);
                wmma::load_matrix_sync(alo[mi], s_alo + (wm * 32 + mi * 16) * SB + ks * 16, SB);
            }
#pragma unroll
            for (int j = 0; j < 4; j++) {
                wmma::fragment<wmma::matrix_b, 16, 16, 16, __nv_bfloat16, wmma::row_major> bhi, blo;
                int col = wn * 64 + j * 16;
                wmma::load_matrix_sync(bhi, s_bhi + (ks * 16) * SB + col, SB);
                wmma::load_matrix_sync(blo, s_blo + (ks * 16) * SB + col, SB);
#pragma unroll
                for (int mi = 0; mi < 2; mi++) {
                    wmma::mma_sync(acc1[mi][j], ahi[mi], bhi, acc1[mi][j]);
                    wmma::mma_sync(acc1[mi][j], alo[mi], bhi, acc1[mi][j]);
                    wmma::mma_sync(acc1[mi][j], ahi[mi], blo, acc1[mi][j]);
                }
            }
        }
        __syncthreads();      // all warps done reading s_b -> reuse as staging

        // stage acc1 fp32 into s_b region
#pragma unroll
        for (int mi = 0; mi < 2; mi++)
#pragma unroll
            for (int j = 0; j < 4; j++)
                wmma::store_matrix_sync(stg + (wm * 32 + mi * 16) * SF + wn * 64 + j * 16,
                                        acc1[mi][j], SF, wmma::mem_row_major);
        __syncthreads();

        // bias + leaky + split -> H chunk (s_h)
        for (int it = tid; it < 128 * 32; it += 256) {
            int r = it >> 5, c4 = (it & 31) << 2;
            float4 v = *reinterpret_cast<float4*>(stg + r * SF + c4);
            float4 bb = *reinterpret_cast<const float4*>(b1 + c * 128 + c4);
            v.x = leaky(v.x + bb.x); v.y = leaky(v.y + bb.y);
            v.z = leaky(v.z + bb.z); v.w = leaky(v.w + bb.w);
            ushort4 h, l;
            bsplit(v.x, h.x, l.x); bsplit(v.y, h.y, l.y);
            bsplit(v.z, h.z, l.z); bsplit(v.w, h.w, l.w);
            *reinterpret_cast<ushort4*>(s_hhi + r * SB + c4) = h;
            *reinterpret_cast<ushort4*>(s_hlo + r * SB + c4) = l;
        }
        __syncthreads();

        // load W3 chunk c into s_b (overwrites staging)
        for (int it = tid; it < 128 * 16; it += 256) {
            int r = it >> 4, c8 = (it & 15) << 3;
            *reinterpret_cast<uint4*>(s_bhi + r * SB + c8) =
                *reinterpret_cast<const uint4*>(g_w3hi + (c * 128 + r) * 128 + c8);
            *reinterpret_cast<uint4*>(s_blo + r * SB + c8) =
                *reinterpret_cast<const uint4*>(g_w3lo + (c * 128 + r) * 128 + c8);
        }
        __syncthreads();

        // mainloop2: acc2 += Hchunk @ W3chunk
#pragma unroll
        for (int ks = 0; ks < 8; ks++) {
            wmma::fragment<wmma::matrix_a, 16, 16, 16, __nv_bfloat16, wmma::row_major> ahi[2], alo[2];
#pragma unroll
            for (int mi = 0; mi < 2; mi++) {
                wmma::load_matrix_sync(ahi[mi], s_hhi + (wm * 32 + mi * 16) * SB + ks * 16, SB);
                wmma::load_matrix_sync(alo[mi], s_hlo + (wm * 32 + mi * 16) * SB + ks * 16, SB);
            }
#pragma unroll
            for (int j = 0; j < 4; j++) {
                wmma::fragment<wmma::matrix_b, 16, 16, 16, __nv_bfloat16, wmma::row_major> bhi, blo;
                int col = wn * 64 + j * 16;
                wmma::load_matrix_sync(bhi, s_bhi + (ks * 16) * SB + col, SB);
                wmma::load_matrix_sync(blo, s_blo + (ks * 16) * SB + col, SB);
#pragma unroll
                for (int mi = 0; mi < 2; mi++) {
                    wmma::mma_sync(acc2[mi][j], ahi[mi], bhi, acc2[mi][j]);
                    wmma::mma_sync(acc2[mi][j], alo[mi], bhi, acc2[mi][j]);
                    wmma::mma_sync(acc2[mi][j], ahi[mi], blo, acc2[mi][j]);
                }
            }
        }
        __syncthreads();      // before next chunk reuses s_b / s_h
    }

    // epilogue: T2 -> g_buf2
#pragma unroll
    for (int mi = 0; mi < 2; mi++)
#pragma unroll
        for (int j = 0; j < 4; j++)
            wmma::store_matrix_sync(stg + (wm * 32 + mi * 16) * SF + wn * 64 + j * 16,
                                    acc2[mi][j], SF, wmma::mem_row_major);
    __syncthreads();

    for (int it = tid; it < 128 * 32; it += 256) {
        int r = it >> 5, c4 = (it & 31) << 2;
        if (base + r >= n) continue;
        float4 v = *reinterpret_cast<float4*>(stg + r * SF + c4);
        *reinterpret_cast<float4*>(g_buf2 + (size_t)(base + r) * 128 + c4) = v;
    }
}

// ---------------- fused pull2 + head -------------------------------------------
// grid ceil(n/64); block 256 = 8 warps. Phase A: each warp pulls 8 nodes from
// g_buf2 (CSR gather), applies b3+leaky, splits into smem. Phase B: FC1 wmma
// (B col-major from gmem) + FC2 reduce.
__global__ void __launch_bounds__(256) k_pull_final(
    const float* __restrict__ b3, const float* __restrict__ fc1b,
    const float* __restrict__ fc2w, const float* __restrict__ fc2b,
    float* __restrict__ out, int n) {
    extern __shared__ __nv_bfloat16 sh[];
    __nv_bfloat16* s_ahi = sh;
    __nv_bfloat16* s_alo = sh + 64 * SB;

    int tid = threadIdx.x;
    int wid = tid >> 5;
    int lane = tid & 31;
    int base = blockIdx.x * 64;

    float4 bb = reinterpret_cast<const float4*>(b3)[lane];

    for (int i = 0; i < 8; i++) {
        int r = wid * 8 + i;
        int node = base + r;
        float4 acc = make_float4(0.f, 0.f, 0.f, 0.f);
        if (node < n) {
            int off = g_off[node], cnt = g_cnt[node];
            float dd = g_dinv[node];
            float4 v = reinterpret_cast<const float4*>(g_buf2 + (size_t)node * 128)[lane];
            acc.x = dd * v.x; acc.y = dd * v.y; acc.z = dd * v.z; acc.w = dd * v.w;
            int j = 0;
            for (; j + 3 < cnt; j += 4) {
                int s0 = g_srt[off + j],     s1 = g_srt[off + j + 1];
                int s2 = g_srt[off + j + 2], s3 = g_srt[off + j + 3];
                float w0 = g_dinv[s0], w1 = g_dinv[s1];
                float w2 = g_dinv[s2], w3 = g_dinv[s3];
                float4 a = reinterpret_cast<const float4*>(g_buf2 + (size_t)s0 * 128)[lane];
                float4 b = reinterpret_cast<const float4*>(g_buf2 + (size_t)s1 * 128)[lane];
                float4 cc = reinterpret_cast<const float4*>(g_buf2 + (size_t)s2 * 128)[lane];
                float4 e = reinterpret_cast<const float4*>(g_buf2 + (size_t)s3 * 128)[lane];
                acc.x += w0 * a.x + w1 * b.x + w2 * cc.x + w3 * e.x;
                acc.y += w0 * a.y + w1 * b.y + w2 * cc.y + w3 * e.y;
                acc.z += w0 * a.z + w1 * b.z + w2 * cc.z + w3 * e.z;
                acc.w += w0 * a.w + w1 * b.w + w2 * cc.w + w3 * e.w;
            }
            for (; j < cnt; j++) {
                int s0 = g_srt[off + j];
                float w0 = g_dinv[s0];
                float4 a = reinterpret_cast<const float4*>(g_buf2 + (size_t)s0 * 128)[lane];
                acc.x += w0 * a.x; acc.y += w0 * a.y; acc.z += w0 * a.z; acc.w += w0 * a.w;
            }
            acc.x = leaky(acc.x * dd + bb.x);
            acc.y = leaky(acc.y * dd + bb.y);
            acc.z = leaky(acc.z * dd + bb.z);
            acc.w = leaky(acc.w * dd + bb.w);
        }
        ushort4 h, l;
        bsplit(acc.x, h.x, l.x); bsplit(acc.y, h.y, l.y);
        bsplit(acc.z, h.z, l.z); bsplit(acc.w, h.w, l.w);
        *reinterpret_cast<ushort4*>(s_ahi + r * SB + lane * 4) = h;
        *reinterpret_cast<ushort4*>(s_alo + r * SB + lane * 4) = l;
    }
    __syncthreads();

    int wm = wid & 1;       // rows wm*32
    int wn = wid >> 1;      // ch cols wn*64
    wmma::fragment<wmma::accumulator, 16, 16, 16, float> acc[2][4];
#pragma unroll
    for (int mi = 0; mi < 2; mi++)
#pragma unroll
        for (int j = 0; j < 4; j++) wmma::fill_fragment(acc[mi][j], 0.f);

#pragma unroll
    for (int ks = 0; ks < 8; ks++) {
        wmma::fragment<wmma::matrix_a, 16, 16, 16, __nv_bfloat16, wmma::row_major> ahi[2], alo[2];
#pragma unroll
        for (int mi = 0; mi < 2; mi++) {
            wmma::load_matrix_sync(ahi[mi], s_ahi + (wm * 32 + mi * 16) * SB + ks * 16, SB);
            wmma::load_matrix_sync(alo[mi], s_alo + (wm * 32 + mi * 16) * SB + ks * 16, SB);
        }
#pragma unroll
        for (int j = 0; j < 4; j++) {
            int col = wn * 64 + j * 16;
            wmma::fragment<wmma::matrix_b, 16, 16, 16, __nv_bfloat16, wmma::col_major> bhi, blo;
            wmma::load_matrix_sync(bhi, g_fc1hi + (size_t)col * 128 + ks * 16, 128);
            wmma::load_matrix_sync(blo, g_fc1lo + (size_t)col * 128 + ks * 16, 128);
#pragma unroll
            for (int mi = 0; mi < 2; mi++) {
                wmma::mma_sync(acc[mi][j], ahi[mi], bhi, acc[mi][j]);
                wmma::mma_sync(acc[mi][j], alo[mi], bhi, acc[mi][j]);
                wmma::mma_sync(acc[mi][j], ahi[mi], blo, acc[mi][j]);
            }
        }
    }
    __syncthreads();   // reuse smem as fp32 epilogue [64][HF]

    float* e = reinterpret_cast<float*>(sh);
#pragma unroll
    for (int mi = 0; mi < 2; mi++)
#pragma unroll
        for (int j = 0; j < 4; j++)
            wmma::store_matrix_sync(e + (wm * 32 + mi * 16) * HF + wn * 64 + j * 16,
                                    acc[mi][j], HF, wmma::mem_row_major);
    __syncthreads();

    {
        int node = tid >> 2;
        int part = tid & 3;
        float s = 0.f;
        const float* er = e + node * HF + part * 64;
#pragma unroll
        for (int c4 = 0; c4 < 16; c4++) {
            float4 v = *reinterpret_cast<const float4*>(er + c4 * 4);
            float4 fb = *reinterpret_cast<const float4*>(fc1b + part * 64 + c4 * 4);
            float4 w2 = *reinterpret_cast<const float4*>(fc2w + part * 64 + c4 * 4);
            s += leaky(v.x + fb.x) * w2.x + leaky(v.y + fb.y) * w2.y
               + leaky(v.z + fb.z) * w2.z + leaky(v.w + fb.w) * w2.w;
        }
        s += __shfl_xor_sync(0xffffffffu, s, 1);
        s += __shfl_xor_sync(0xffffffffu, s, 2);
        if (part == 0 && base + node < n)
            out[base + node] = s + fc2b[0];
    }
}

// ---------------------------------------------------------------------------
extern "C" void kernel_launch(void* const* d_in, const int* in_sizes, int n_in,
                              void* d_out, int out_size) {
    const float* x    = (const float*)d_in[0];
    const int*   ei   = (const int*)d_in[1];   // int32 (JAX x64 disabled)
    const float* W1   = (const float*)d_in[2];
    const float* b1   = (const float*)d_in[3];
    const float* W3   = (const float*)d_in[4];
    const float* b3   = (const float*)d_in[5];
    const float* fc1w = (const float*)d_in[6];
    const float* fc1b = (const float*)d_in[7];
    const float* fc2w = (const float*)d_in[8];
    const float* fc2b = (const float*)d_in[9];
    float* out = (float*)d_out;

    int n = in_sizes[0] / 128;
    int E = in_sizes[1] / 2;
    int mt = (n + 127) / 128;
    int mt64 = (n + 63) / 64;

    static int smem_set = 0;
    if (!smem_set) {
        cudaFuncSetAttribute(k_wgemm12, cudaFuncAttributeMaxDynamicSharedMemorySize,
                             WG_TOTAL_BYTES);
        cudaFuncSetAttribute(k_pull_final, cudaFuncAttributeMaxDynamicSharedMemorySize,
                             HS_TOTAL_BYTES);
        smem_set = 1;
    }

    // CSR build
    k_zero<<<(n + 255) / 256, 256>>>(n);
    k_hist<<<(E + 255) / 256, 256>>>(ei, E);
    k_scan<<<1, 1024>>>(n);
    k_scatter<<<(E + 255) / 256, 256>>>(ei, E);

    // merged weight prep
    k_prep<<<(163840 + 255) / 256, 256>>>(W1, W3, fc1w);

    // A1 = Ahat @ x -> g_buf1
    k_pull<<<(n * 32 + 255) / 256, 256>>>(x, n);
    // T2 = leaky(A1@W1+b1) @ W3 -> g_buf2  (fused, no H1 round-trip)
    k_wgemm12<<<mt, 256, WG_TOTAL_BYTES>>>(b1, n);
    // out = FC2(leaky(FC1(leaky(Ahat@T2 + b3)))), pull fused into head
    k_pull_final<<<mt64, 256, HS_TOTAL_BYTES>>>(b3, fc1b, fc2w, fc2b, out, n);
}